// round 2
// baseline (speedup 1.0000x reference)
#include <cuda_runtime.h>

#define BB 16
#define SS 4096
#define HH 1024
#define QD 1024
#define KD 2048
#define SSPLIT 4
#define SCHUNK (SS / SSPLIT)   // 1024

// Scratch (no allocation allowed in kernel_launch)
__device__ float g_q[BB * HH];                 // 64 KB
__device__ float g_scores[BB * SS];            // 256 KB
__device__ float g_partial[SSPLIT * BB * KD];  // 512 KB

// tanh via MUFU.EX2 + MUFU.RCP: abs err ~1e-7, saturates correctly at +/-inf
__device__ __forceinline__ float fast_tanh(float x) {
    float e = __expf(2.0f * x);
    return 1.0f - __fdividef(2.0f, e + 1.0f);
}

// ---------------------------------------------------------------------------
// K1: q[b,h] = sum_q query[b,q] * Wq[h,q]   (warp per output)
// ---------------------------------------------------------------------------
__global__ void k1_proj(const float* __restrict__ query, const float* __restrict__ Wq) {
    int warp = (blockIdx.x * blockDim.x + threadIdx.x) >> 5;
    int lane = threadIdx.x & 31;
    if (warp >= BB * HH) return;
    int b = warp >> 10;        // / HH
    int h = warp & (HH - 1);
    const float4* q4 = (const float4*)(query + (size_t)b * QD);
    const float4* w4 = (const float4*)(Wq + (size_t)h * QD);
    float acc = 0.f;
#pragma unroll
    for (int i = 0; i < QD / 128; i++) {
        float4 a = q4[lane + i * 32];
        float4 w = w4[lane + i * 32];
        acc += a.x * w.x + a.y * w.y + a.z * w.z + a.w * w.w;
    }
#pragma unroll
    for (int o = 16; o; o >>= 1) acc += __shfl_xor_sync(0xffffffffu, acc, o);
    if (lane == 0) g_q[warp] = acc;
}

// ---------------------------------------------------------------------------
// K2: scores[b,s] = sum_h w[h] * tanh(q[b,h] + pk[b,s,h])   (warp per row)
// Streams 256 MB of proj_key; q and w_energy hit L2.
// ---------------------------------------------------------------------------
__global__ void k2_scores(const float* __restrict__ pk, const float* __restrict__ w_energy) {
    int warp = (blockIdx.x * blockDim.x + threadIdx.x) >> 5;  // == b*SS + s
    int lane = threadIdx.x & 31;
    int b = warp >> 12;  // / SS
    const float4* p4 = (const float4*)(pk + (size_t)warp * HH);
    const float4* q4 = (const float4*)(g_q + (size_t)b * HH);
    const float4* w4 = (const float4*)w_energy;
    float acc = 0.f;
#pragma unroll
    for (int i = 0; i < HH / 128; i++) {
        float4 p = p4[lane + i * 32];
        float4 q = q4[lane + i * 32];
        float4 w = w4[lane + i * 32];
        acc += w.x * fast_tanh(q.x + p.x);
        acc += w.y * fast_tanh(q.y + p.y);
        acc += w.z * fast_tanh(q.z + p.z);
        acc += w.w * fast_tanh(q.w + p.w);
    }
#pragma unroll
    for (int o = 16; o; o >>= 1) acc += __shfl_xor_sync(0xffffffffu, acc, o);
    if (lane == 0) g_scores[warp] = acc;
}

// ---------------------------------------------------------------------------
// K3: masked softmax over S per batch. One block (1024 thr) per b.
// alphas written directly into d_out (offset BB*KD).
// ---------------------------------------------------------------------------
__global__ void k3_softmax(const int* __restrict__ mask, float* __restrict__ alphas) {
    int b = blockIdx.x;
    int tid = threadIdx.x;
    int lane = tid & 31, wid = tid >> 5;
    __shared__ float red[32];
    __shared__ float bcast;

    float v[4];
    float mx = -INFINITY;
#pragma unroll
    for (int i = 0; i < 4; i++) {
        int s = tid + i * 1024;
        float sc = g_scores[b * SS + s];
        v[i] = (mask[b * SS + s] == 0) ? -INFINITY : sc;
        mx = fmaxf(mx, v[i]);
    }
#pragma unroll
    for (int o = 16; o; o >>= 1) mx = fmaxf(mx, __shfl_xor_sync(0xffffffffu, mx, o));
    if (lane == 0) red[wid] = mx;
    __syncthreads();
    if (tid < 32) {
        float m = red[tid];
#pragma unroll
        for (int o = 16; o; o >>= 1) m = fmaxf(m, __shfl_xor_sync(0xffffffffu, m, o));
        if (tid == 0) bcast = m;
    }
    __syncthreads();
    mx = bcast;

    float e[4];
    float sum = 0.f;
#pragma unroll
    for (int i = 0; i < 4; i++) {
        e[i] = __expf(v[i] - mx);   // exp(-inf) == 0 handles mask
        sum += e[i];
    }
    __syncthreads();  // red reuse
#pragma unroll
    for (int o = 16; o; o >>= 1) sum += __shfl_xor_sync(0xffffffffu, sum, o);
    if (lane == 0) red[wid] = sum;
    __syncthreads();
    if (tid < 32) {
        float m = red[tid];
#pragma unroll
        for (int o = 16; o; o >>= 1) m += __shfl_xor_sync(0xffffffffu, m, o);
        if (tid == 0) bcast = m;
    }
    __syncthreads();
    float inv = 1.0f / bcast;
#pragma unroll
    for (int i = 0; i < 4; i++) {
        int s = tid + i * 1024;
        alphas[b * SS + s] = e[i] * inv;
    }
}

// ---------------------------------------------------------------------------
// K4: partial context. grid = (KD/256, BB, SSPLIT). Streams 512 MB of value.
// ---------------------------------------------------------------------------
__global__ void k4_ctx(const float* __restrict__ value, const float* __restrict__ alphas) {
    __shared__ float a[SCHUNK];
    int b = blockIdx.y;
    int ssec = blockIdx.z;
    int k = blockIdx.x * blockDim.x + threadIdx.x;
    int s0 = ssec * SCHUNK;

    for (int i = threadIdx.x; i < SCHUNK; i += blockDim.x)
        a[i] = alphas[b * SS + s0 + i];
    __syncthreads();

    const float* vp = value + ((size_t)b * SS + s0) * KD + k;
    float acc = 0.f;
#pragma unroll 8
    for (int s = 0; s < SCHUNK; s++)
        acc += a[s] * vp[(size_t)s * KD];

    g_partial[((size_t)ssec * BB + b) * KD + k] = acc;
}

// ---------------------------------------------------------------------------
// K5: reduce SSPLIT partials -> context (fixed order => deterministic)
// ---------------------------------------------------------------------------
__global__ void k5_reduce(float* __restrict__ ctx) {
    int i = blockIdx.x * blockDim.x + threadIdx.x;  // 0 .. BB*KD-1
    float acc = 0.f;
#pragma unroll
    for (int j = 0; j < SSPLIT; j++) acc += g_partial[(size_t)j * BB * KD + i];
    ctx[i] = acc;
}

extern "C" void kernel_launch(void* const* d_in, const int* in_sizes, int n_in,
                              void* d_out, int out_size) {
    const int*   mask     = (const int*)d_in[0];
    const float* query    = (const float*)d_in[1];
    const float* proj_key = (const float*)d_in[2];
    const float* value    = (const float*)d_in[3];
    const float* Wq       = (const float*)d_in[4];
    const float* w_energy = (const float*)d_in[5];

    float* out    = (float*)d_out;
    float* ctx    = out;              // (B,1,K) = 32768 floats
    float* alphas = out + BB * KD;    // (B,1,S) = 65536 floats

    k1_proj<<<BB * HH / 8, 256>>>(query, Wq);
    k2_scores<<<BB * SS / 8, 256>>>(proj_key, w_energy);
    k3_softmax<<<BB, 1024>>>(mask, alphas);
    k4_ctx<<<dim3(KD / 256, BB, SSPLIT), 256>>>(value, alphas);
    k5_reduce<<<BB * KD / 256, 256>>>(ctx);
}

// round 3
// speedup vs baseline: 1.1373x; 1.1373x over previous
#include <cuda_runtime.h>

#define BB 16
#define SS 4096
#define HH 1024
#define QD 1024
#define KD 2048
#define SSPLIT 32
#define SCHUNK (SS / SSPLIT)   // 128

// Scratch (no allocation allowed in kernel_launch)
__device__ float g_q[BB * HH];                 // 64 KB
__device__ float g_scores[BB * SS];            // 256 KB
__device__ float g_partial[SSPLIT * BB * KD];  // 4 MB

// tanh via MUFU.EX2 + MUFU.RCP: abs err ~1e-7, saturates correctly at +/-inf
__device__ __forceinline__ float fast_tanh(float x) {
    float e = __expf(2.0f * x);
    return 1.0f - __fdividef(2.0f, e + 1.0f);
}

// ---------------------------------------------------------------------------
// K1: q[b,h] = sum_q query[b,q] * Wq[h,q]   (warp per output)
// ---------------------------------------------------------------------------
__global__ void k1_proj(const float* __restrict__ query, const float* __restrict__ Wq) {
    int warp = (blockIdx.x * blockDim.x + threadIdx.x) >> 5;
    int lane = threadIdx.x & 31;
    if (warp >= BB * HH) return;
    int b = warp >> 10;        // / HH
    int h = warp & (HH - 1);
    const float4* q4 = (const float4*)(query + (size_t)b * QD);
    const float4* w4 = (const float4*)(Wq + (size_t)h * QD);
    float acc = 0.f;
#pragma unroll
    for (int i = 0; i < QD / 128; i++) {
        float4 a = q4[lane + i * 32];
        float4 w = w4[lane + i * 32];
        acc += a.x * w.x + a.y * w.y + a.z * w.z + a.w * w.w;
    }
#pragma unroll
    for (int o = 16; o; o >>= 1) acc += __shfl_xor_sync(0xffffffffu, acc, o);
    if (lane == 0) g_q[warp] = acc;
}

// ---------------------------------------------------------------------------
// K2: scores[b,s] = sum_h w[h] * tanh(q[b,h] + pk[b,s,h])   (warp per row)
// Streams 256 MB of proj_key; q and w_energy hit L2.
// ---------------------------------------------------------------------------
__global__ void k2_scores(const float* __restrict__ pk, const float* __restrict__ w_energy) {
    int warp = (blockIdx.x * blockDim.x + threadIdx.x) >> 5;  // == b*SS + s
    int lane = threadIdx.x & 31;
    int b = warp >> 12;  // / SS
    const float4* p4 = (const float4*)(pk + (size_t)warp * HH);
    const float4* q4 = (const float4*)(g_q + (size_t)b * HH);
    const float4* w4 = (const float4*)w_energy;
    float acc = 0.f;
#pragma unroll
    for (int i = 0; i < HH / 128; i++) {
        float4 p = p4[lane + i * 32];
        float4 q = q4[lane + i * 32];
        float4 w = w4[lane + i * 32];
        acc += w.x * fast_tanh(q.x + p.x);
        acc += w.y * fast_tanh(q.y + p.y);
        acc += w.z * fast_tanh(q.z + p.z);
        acc += w.w * fast_tanh(q.w + p.w);
    }
#pragma unroll
    for (int o = 16; o; o >>= 1) acc += __shfl_xor_sync(0xffffffffu, acc, o);
    if (lane == 0) g_scores[warp] = acc;
}

// ---------------------------------------------------------------------------
// K3: masked softmax over S per batch. One block (1024 thr) per b.
// alphas written directly into d_out (offset BB*KD).
// ---------------------------------------------------------------------------
__global__ void k3_softmax(const int* __restrict__ mask, float* __restrict__ alphas) {
    int b = blockIdx.x;
    int tid = threadIdx.x;
    int lane = tid & 31, wid = tid >> 5;
    __shared__ float red[32];
    __shared__ float bcast;

    float v[4];
    float mx = -INFINITY;
#pragma unroll
    for (int i = 0; i < 4; i++) {
        int s = tid + i * 1024;
        float sc = g_scores[b * SS + s];
        v[i] = (mask[b * SS + s] == 0) ? -INFINITY : sc;
        mx = fmaxf(mx, v[i]);
    }
#pragma unroll
    for (int o = 16; o; o >>= 1) mx = fmaxf(mx, __shfl_xor_sync(0xffffffffu, mx, o));
    if (lane == 0) red[wid] = mx;
    __syncthreads();
    if (tid < 32) {
        float m = red[tid];
#pragma unroll
        for (int o = 16; o; o >>= 1) m = fmaxf(m, __shfl_xor_sync(0xffffffffu, m, o));
        if (tid == 0) bcast = m;
    }
    __syncthreads();
    mx = bcast;

    float e[4];
    float sum = 0.f;
#pragma unroll
    for (int i = 0; i < 4; i++) {
        e[i] = __expf(v[i] - mx);   // exp(-inf) == 0 handles mask
        sum += e[i];
    }
    __syncthreads();  // red reuse
#pragma unroll
    for (int o = 16; o; o >>= 1) sum += __shfl_xor_sync(0xffffffffu, sum, o);
    if (lane == 0) red[wid] = sum;
    __syncthreads();
    if (tid < 32) {
        float m = red[tid];
#pragma unroll
        for (int o = 16; o; o >>= 1) m += __shfl_xor_sync(0xffffffffu, m, o);
        if (tid == 0) bcast = m;
    }
    __syncthreads();
    float inv = 1.0f / bcast;
#pragma unroll
    for (int i = 0; i < 4; i++) {
        int s = tid + i * 1024;
        alphas[b * SS + s] = e[i] * inv;
    }
}

// ---------------------------------------------------------------------------
// K4: partial context, float4 wide. grid = (KD/1024, BB, SSPLIT) = 1024 blocks.
// Each thread owns 4 k-columns; streams 512 MB of value at high MLP.
// ---------------------------------------------------------------------------
__global__ void __launch_bounds__(256) k4_ctx(const float* __restrict__ value,
                                              const float* __restrict__ alphas) {
    __shared__ float a[SCHUNK];
    int b = blockIdx.y;
    int ssec = blockIdx.z;
    int k4i = blockIdx.x * blockDim.x + threadIdx.x;  // float4 column index
    int s0 = ssec * SCHUNK;

    if (threadIdx.x < SCHUNK)
        a[threadIdx.x] = alphas[b * SS + s0 + threadIdx.x];
    __syncthreads();

    const float4* vp = (const float4*)(value + ((size_t)b * SS + s0) * KD) + k4i;
    float4 acc = make_float4(0.f, 0.f, 0.f, 0.f);
#pragma unroll 8
    for (int s = 0; s < SCHUNK; s++) {
        float4 v = vp[(size_t)s * (KD / 4)];
        float al = a[s];
        acc.x += al * v.x;
        acc.y += al * v.y;
        acc.z += al * v.z;
        acc.w += al * v.w;
    }

    float4* pp = (float4*)(g_partial + ((size_t)ssec * BB + b) * KD) + k4i;
    *pp = acc;
}

// ---------------------------------------------------------------------------
// K5: reduce SSPLIT partials -> context (fixed order => deterministic)
// ---------------------------------------------------------------------------
__global__ void k5_reduce(float* __restrict__ ctx) {
    int i = blockIdx.x * blockDim.x + threadIdx.x;  // float4 index, 0 .. BB*KD/4-1
    const float4* p = (const float4*)g_partial;
    float4 acc = make_float4(0.f, 0.f, 0.f, 0.f);
#pragma unroll
    for (int j = 0; j < SSPLIT; j++) {
        float4 v = p[(size_t)j * (BB * KD / 4) + i];
        acc.x += v.x; acc.y += v.y; acc.z += v.z; acc.w += v.w;
    }
    ((float4*)ctx)[i] = acc;
}

extern "C" void kernel_launch(void* const* d_in, const int* in_sizes, int n_in,
                              void* d_out, int out_size) {
    const int*   mask     = (const int*)d_in[0];
    const float* query    = (const float*)d_in[1];
    const float* proj_key = (const float*)d_in[2];
    const float* value    = (const float*)d_in[3];
    const float* Wq       = (const float*)d_in[4];
    const float* w_energy = (const float*)d_in[5];

    float* out    = (float*)d_out;
    float* ctx    = out;              // (B,1,K) = 32768 floats
    float* alphas = out + BB * KD;    // (B,1,S) = 65536 floats

    k1_proj<<<BB * HH / 8, 256>>>(query, Wq);
    k2_scores<<<BB * SS / 8, 256>>>(proj_key, w_energy);
    k3_softmax<<<BB, 1024>>>(mask, alphas);
    k4_ctx<<<dim3(KD / 1024, BB, SSPLIT), 256>>>(value, alphas);
    k5_reduce<<<BB * KD / 4 / 256, 256>>>(ctx);
}